// round 8
// baseline (speedup 1.0000x reference)
#include <cuda_runtime.h>
#include <math.h>
#include <stdint.h>

#define SEQ   2048
#define HID   2048
#define HD    128
#define NH    16

// Scratch (device globals: allocation-free rule)
__device__ float g_Q[SEQ * HID];
__device__ float g_K[SEQ * HID];
__device__ float g_V[SEQ * HID];
__device__ float g_O[SEQ * HID];
__device__ float g_Xr[SEQ * HID];
__device__ float g_W0[HID * HID];
__device__ float g_W1[HID * HID];
__device__ float g_W2[HID * HID];
__device__ float g_W3[HID * HID];

// ===========================================================================
// Helpers
// ===========================================================================
__device__ __forceinline__ uint32_t smem_u32(const void* p) {
    uint32_t a;
    asm("{ .reg .u64 t; cvta.to.shared.u64 t, %1; cvt.u32.u64 %0, t; }"
        : "=r"(a) : "l"(p));
    return a;
}
__device__ __forceinline__ void cp_async16(uint32_t dst, const void* src) {
    asm volatile("cp.async.cg.shared.global [%0], [%1], 16;" :: "r"(dst), "l"(src));
}
#define CP_COMMIT() asm volatile("cp.async.commit_group;" ::: "memory")
#define CP_WAIT(n)  asm volatile("cp.async.wait_group %0;" :: "n"(n) : "memory")

__device__ __forceinline__ uint32_t f2tf(float x) {
    uint32_t r;
    asm("cvt.rna.tf32.f32 %0, %1;" : "=r"(r) : "f"(x));
    return r;
}
__device__ __forceinline__ uint32_t shfl_u32(uint32_t v, int src) {
    return __shfl_sync(0xffffffffu, v, src);
}

// ldmatrix x4 (b16 view; moves 4x (8 rows x 16B) — tf32 fragment trick)
__device__ __forceinline__ void ldsm_x4(uint32_t r[4], uint32_t addr) {
    asm volatile("ldmatrix.sync.aligned.m8n8.x4.shared.b16 {%0,%1,%2,%3}, [%4];"
        : "=r"(r[0]), "=r"(r[1]), "=r"(r[2]), "=r"(r[3]) : "r"(addr));
}

// C[16x8] += A[16x8] * B[8x8]^T   (tf32, fp32 accum)
__device__ __forceinline__ void mma_tf32(float c[4], const uint32_t a[4],
                                         const uint32_t b[2]) {
    asm volatile(
        "mma.sync.aligned.m16n8k8.row.col.f32.tf32.tf32.f32 "
        "{%0,%1,%2,%3}, {%4,%5,%6,%7}, {%8,%9}, {%0,%1,%2,%3};"
        : "+f"(c[0]), "+f"(c[1]), "+f"(c[2]), "+f"(c[3])
        : "r"(a[0]), "r"(a[1]), "r"(a[2]), "r"(a[3]), "r"(b[0]), "r"(b[1]));
}

// ===========================================================================
// Fused tf32 rounding prepass: one launch rounds all 5 tensors.
// ===========================================================================
__global__ __launch_bounds__(256) void round_tf32_5(
    const float4* __restrict__ i0, const float4* __restrict__ i1,
    const float4* __restrict__ i2, const float4* __restrict__ i3,
    const float4* __restrict__ i4,
    float4* __restrict__ o0, float4* __restrict__ o1,
    float4* __restrict__ o2, float4* __restrict__ o3,
    float4* __restrict__ o4, int n4)
{
    const int z = blockIdx.y;
    const float4* in  = (z == 0) ? i0 : (z == 1) ? i1 : (z == 2) ? i2
                       : (z == 3) ? i3 : i4;
    float4* out       = (z == 0) ? o0 : (z == 1) ? o1 : (z == 2) ? o2
                       : (z == 3) ? o3 : o4;
    int i = blockIdx.x * blockDim.x + threadIdx.x;
    if (i >= n4) return;
    float4 v = in[i];
    v.x = __uint_as_float(f2tf(v.x));
    v.y = __uint_as_float(f2tf(v.y));
    v.z = __uint_as_float(f2tf(v.z));
    v.w = __uint_as_float(f2tf(v.w));
    out[i] = v;
}

// ===========================================================================
// tf32 mma.sync GEMM core:  C[M,N] = A[M,K] @ B[N,K]^T + bias[N]
// CTA 128x256, 8 warps (2x4) of 64x64, BK=32, 3-stage cp.async,
// ldmatrix.x4 fragment loads.  Per k8 step: 8 LDSM + 32 HMMA per warp.
// ===========================================================================
#define BM 128
#define BN 256
#define BK 32
#define NST 3
#define ROWP 36
#define ATF (BM * ROWP)                    // 4608
#define BTF (BN * ROWP)                    // 9216
#define STF (ATF + BTF)                    // 13824 floats / stage
#define GEMM_SMEM_BYTES (NST * STF * 4)    // 165888

__device__ __forceinline__ void gemm_load_stage(
    const float* __restrict__ Ab, const float* __restrict__ Bb,
    float* sm, int slot, int k0, int tid)
{
    const uint32_t sbase = smem_u32(sm) + (uint32_t)(slot * STF) * 4u;
#pragma unroll
    for (int it = 0; it < 12; it++) {
        const int idx = tid + it * 256;       // 0..3071
        const int r = idx >> 3;               // 0..383  (A rows 0..127, B rows 128..383)
        const int q = idx & 7;
        const float* src = (r < BM) ? (Ab + (size_t)r * HID + k0 + q * 4)
                                    : (Bb + (size_t)(r - BM) * HID + k0 + q * 4);
        cp_async16(sbase + (uint32_t)(r * ROWP + q * 4) * 4u, src);
    }
}

template <bool RND>
__device__ __forceinline__ void gemm_body(
    const float* __restrict__ A, const float* __restrict__ B,
    const float* __restrict__ bias, float* __restrict__ C,
    float* sm, int row0, int col0)
{
    const int tid  = threadIdx.x;
    const int wid  = tid >> 5;
    const int lane = tid & 31;
    const int lr   = lane >> 2;
    const int lc   = lane & 3;
    const int l15  = lane & 15;
    const int lcol = (lane >> 4) << 2;
    const int wm   = (wid >> 2) * 64;      // 0 / 64
    const int wn   = (wid & 3) * 64;       // 0 / 64 / 128 / 192

    const float* Ab = A + (size_t)row0 * HID;
    const float* Bb = B + (size_t)col0 * HID;

    float acc[4][8][4];
#pragma unroll
    for (int mt = 0; mt < 4; mt++)
#pragma unroll
        for (int nt = 0; nt < 8; nt++)
#pragma unroll
            for (int i = 0; i < 4; i++) acc[mt][nt][i] = 0.0f;

#pragma unroll
    for (int s = 0; s < NST - 1; s++) {
        gemm_load_stage(Ab, Bb, sm, s, s * BK, tid);
        CP_COMMIT();
    }

    const uint32_t sbase = smem_u32(sm);
    const int KCH = HID / BK;   // 64
    for (int j = 0; j < KCH; j++) {
        if (j + NST - 1 < KCH) {
            gemm_load_stage(Ab, Bb, sm, (j + NST - 1) % NST, (j + NST - 1) * BK, tid);
        }
        CP_COMMIT();
        CP_WAIT(NST - 1);
        __syncthreads();

        const uint32_t sa = sbase + (uint32_t)((j % NST) * STF) * 4u;
        const uint32_t sb = sa + (uint32_t)ATF * 4u;

#pragma unroll
        for (int kk = 0; kk < BK; kk += 8) {
            uint32_t af[4][4], bf[8][2];
#pragma unroll
            for (int mt = 0; mt < 4; mt++)
                ldsm_x4(af[mt],
                        sa + (uint32_t)((wm + mt * 16 + l15) * ROWP + kk + lcol) * 4u);
#pragma unroll
            for (int np = 0; np < 4; np++) {
                uint32_t t[4];
                ldsm_x4(t,
                        sb + (uint32_t)((wn + np * 16 + l15) * ROWP + kk + lcol) * 4u);
                bf[2 * np + 0][0] = t[0];
                bf[2 * np + 1][0] = t[1];
                bf[2 * np + 0][1] = t[2];
                bf[2 * np + 1][1] = t[3];
            }
#pragma unroll
            for (int mt = 0; mt < 4; mt++)
#pragma unroll
                for (int nt = 0; nt < 8; nt++)
                    mma_tf32(acc[mt][nt], af[mt], bf[nt]);
        }
        __syncthreads();
    }

#pragma unroll
    for (int mt = 0; mt < 4; mt++) {
#pragma unroll
        for (int half = 0; half < 2; half++) {
            const int r = row0 + wm + mt * 16 + lr + half * 8;
            float* crow = C + (size_t)r * HID;
#pragma unroll
            for (int nt = 0; nt < 8; nt++) {
                const int c = col0 + wn + nt * 8 + 2 * lc;
                float2 v;
                v.x = acc[mt][nt][half * 2 + 0] + bias[c];
                v.y = acc[mt][nt][half * 2 + 1] + bias[c + 1];
                if (RND) {
                    v.x = __uint_as_float(f2tf(v.x));
                    v.y = __uint_as_float(f2tf(v.y));
                }
                *(float2*)(crow + c) = v;
            }
        }
    }
}

// Fused QKV projection: blockIdx.z selects weight/bias/output.
__global__ __launch_bounds__(256, 1) void gemm_qkv(
    const float* __restrict__ A,
    const float* __restrict__ W0, const float* __restrict__ W1,
    const float* __restrict__ W2,
    const float* __restrict__ b0, const float* __restrict__ b1,
    const float* __restrict__ b2,
    float* __restrict__ C0, float* __restrict__ C1, float* __restrict__ C2)
{
    extern __shared__ float sm[];
    const int z = blockIdx.z;
    const float* B    = (z == 0) ? W0 : (z == 1) ? W1 : W2;
    const float* bias = (z == 0) ? b0 : (z == 1) ? b1 : b2;
    float* C          = (z == 0) ? C0 : (z == 1) ? C1 : C2;
    gemm_body<true>(A, B, bias, C, sm, blockIdx.y * BM, blockIdx.x * BN);
}

// Single GEMM (output projection)
__global__ __launch_bounds__(256, 1) void gemm_single(
    const float* __restrict__ A, const float* __restrict__ B,
    const float* __restrict__ bias, float* __restrict__ C)
{
    extern __shared__ float sm[];
    gemm_body<false>(A, B, bias, C, sm, blockIdx.y * BM, blockIdx.x * BN);
}

// ===========================================================================
// Flash attention, tf32 mma.sync (unchanged from round 7).
// ===========================================================================
#define FAQ 128
#define FSK 64
#define KP  132
#define VP  136
#define KTILE_FLOATS (FSK * KP)
#define VTILE_FLOATS (FSK * VP)
#define FSTAGE (KTILE_FLOATS + VTILE_FLOATS)
#define FLASH_SMEM_BYTES (2 * FSTAGE * 4)   // 137216

__device__ __forceinline__ void flash_load_kv(
    const float* __restrict__ K, const float* __restrict__ V,
    float* sm, int slot, int kt, int hcol, int tid)
{
    float* Ks = sm + slot * FSTAGE;
    float* Vs = Ks + KTILE_FLOATS;
    const uint32_t ka = smem_u32(Ks);
    const uint32_t va = smem_u32(Vs);
    const int base = kt * FSK;
#pragma unroll
    for (int it = 0; it < 8; it++) {
        const int idx = tid + it * 256;
        const int row = idx >> 5;
        const int q   = idx & 31;
        cp_async16(ka + (uint32_t)(row * KP + q * 4) * 4u,
                   K + (size_t)(base + row) * HID + hcol + q * 4);
        cp_async16(va + (uint32_t)(row * VP + q * 4) * 4u,
                   V + (size_t)(base + row) * HID + hcol + q * 4);
    }
}

__global__ __launch_bounds__(256, 1) void flash_attn_tf32(
    const float* __restrict__ Q, const float* __restrict__ K,
    const float* __restrict__ V, float* __restrict__ O,
    const float* __restrict__ order_gate, const float* __restrict__ justice_gate)
{
    extern __shared__ float fsm[];

    const int tid  = threadIdx.x;
    const int wid  = tid >> 5;
    const int lane = tid & 31;
    const int lr   = lane >> 2;
    const int lc   = lane & 3;
    const int l15  = lane & 15;
    const int lcol = (lane >> 4) << 2;
    const int hcol = blockIdx.y * HD;
    const int qbase = blockIdx.x * FAQ + wid * 16;

    const float sig_j = 1.0f / (1.0f + __expf(-justice_gate[0]));
    const float sig_o = 1.0f / (1.0f + __expf(-order_gate[0]));
    const float alpha = (1.0f - 0.1f * sig_j) * rsqrtf((float)HD);
    const float obias = sig_o * 0.05f / (float)SEQ;

    uint32_t qf[16][4];
    {
        const float* Qb = Q + (size_t)qbase * HID + hcol;
#pragma unroll
        for (int ks = 0; ks < 16; ks++) {
            qf[ks][0] = __float_as_uint(Qb[(size_t)lr * HID + ks * 8 + lc]);
            qf[ks][1] = __float_as_uint(Qb[(size_t)(lr + 8) * HID + ks * 8 + lc]);
            qf[ks][2] = __float_as_uint(Qb[(size_t)lr * HID + ks * 8 + lc + 4]);
            qf[ks][3] = __float_as_uint(Qb[(size_t)(lr + 8) * HID + ks * 8 + lc + 4]);
        }
    }

    float m0 = -1.0e30f, m1 = -1.0e30f, l0 = 0.0f, l1 = 0.0f;
    float of[16][4];
#pragma unroll
    for (int nt = 0; nt < 16; nt++)
#pragma unroll
        for (int i = 0; i < 4; i++) of[nt][i] = 0.0f;

    flash_load_kv(K, V, fsm, 0, 0, hcol, tid);
    CP_COMMIT();

    const int NT = SEQ / FSK;   // 32
    for (int kt = 0; kt < NT; kt++) {
        if (kt + 1 < NT) {
            flash_load_kv(K, V, fsm, (kt + 1) & 1, kt + 1, hcol, tid);
            CP_COMMIT();
            CP_WAIT(1);
        } else {
            CP_WAIT(0);
        }
        __syncthreads();

        const float* Ks = fsm + (kt & 1) * FSTAGE;
        const float* Vs = Ks + KTILE_FLOATS;
        const uint32_t ksa = smem_u32(Ks);

        float sf[8][4];
#pragma unroll
        for (int nt = 0; nt < 8; nt++)
#pragma unroll
            for (int i = 0; i < 4; i++) sf[nt][i] = 0.0f;

#pragma unroll
        for (int ks = 0; ks < 16; ks++) {
            uint32_t bf[8][2];
#pragma unroll
            for (int ng = 0; ng < 4; ng++) {
                uint32_t t[4];
                ldsm_x4(t, ksa + (uint32_t)((ng * 16 + l15) * KP + ks * 8 + lcol) * 4u);
                bf[2 * ng + 0][0] = t[0];
                bf[2 * ng + 1][0] = t[1];
                bf[2 * ng + 0][1] = t[2];
                bf[2 * ng + 1][1] = t[3];
            }
#pragma unroll
            for (int nt = 0; nt < 8; nt++)
                mma_tf32(sf[nt], qf[ks], bf[nt]);
        }

        float rmax0 = -1.0e30f, rmax1 = -1.0e30f;
#pragma unroll
        for (int nt = 0; nt < 8; nt++) {
            const float col0 = (float)(kt * FSK + nt * 8 + 2 * lc);
            sf[nt][0] = fmaf(sf[nt][0], alpha, obias * col0);
            sf[nt][1] = fmaf(sf[nt][1], alpha, obias * (col0 + 1.0f));
            sf[nt][2] = fmaf(sf[nt][2], alpha, obias * col0);
            sf[nt][3] = fmaf(sf[nt][3], alpha, obias * (col0 + 1.0f));
            rmax0 = fmaxf(rmax0, fmaxf(sf[nt][0], sf[nt][1]));
            rmax1 = fmaxf(rmax1, fmaxf(sf[nt][2], sf[nt][3]));
        }
#pragma unroll
        for (int off = 1; off < 4; off <<= 1) {
            rmax0 = fmaxf(rmax0, __shfl_xor_sync(0xffffffffu, rmax0, off));
            rmax1 = fmaxf(rmax1, __shfl_xor_sync(0xffffffffu, rmax1, off));
        }
        const float m0n = fmaxf(m0, rmax0);
        const float m1n = fmaxf(m1, rmax1);
        const float corr0 = __expf(m0 - m0n);
        const float corr1 = __expf(m1 - m1n);

        float rsum0 = 0.0f, rsum1 = 0.0f;
        uint32_t pf[8][4];
#pragma unroll
        for (int nt = 0; nt < 8; nt++) {
            const float e0 = __expf(sf[nt][0] - m0n);
            const float e1 = __expf(sf[nt][1] - m0n);
            const float e2 = __expf(sf[nt][2] - m1n);
            const float e3 = __expf(sf[nt][3] - m1n);
            rsum0 += e0 + e1;
            rsum1 += e2 + e3;
            pf[nt][0] = f2tf(e0); pf[nt][1] = f2tf(e1);
            pf[nt][2] = f2tf(e2); pf[nt][3] = f2tf(e3);
        }
#pragma unroll
        for (int off = 1; off < 4; off <<= 1) {
            rsum0 += __shfl_xor_sync(0xffffffffu, rsum0, off);
            rsum1 += __shfl_xor_sync(0xffffffffu, rsum1, off);
        }
        l0 = l0 * corr0 + rsum0; m0 = m0n;
        l1 = l1 * corr1 + rsum1; m1 = m1n;

#pragma unroll
        for (int nt = 0; nt < 16; nt++) {
            of[nt][0] *= corr0; of[nt][1] *= corr0;
            of[nt][2] *= corr1; of[nt][3] *= corr1;
        }

        const int src0 = lr * 4 + (lc >> 1);
        const bool odd = (lc & 1);
#pragma unroll
        for (int kp = 0; kp < 8; kp++) {
            uint32_t pa[4];
            {
                uint32_t v0 = shfl_u32(pf[kp][0], src0);
                uint32_t v1 = shfl_u32(pf[kp][1], src0);
                pa[0] = odd ? v1 : v0;
                uint32_t v2 = shfl_u32(pf[kp][2], src0);
                uint32_t v3 = shfl_u32(pf[kp][3], src0);
                pa[1] = odd ? v3 : v2;
                uint32_t w0 = shfl_u32(pf[kp][0], src0 + 2);
                uint32_t w1 = shfl_u32(pf[kp][1], src0 + 2);
                pa[2] = odd ? w1 : w0;
                uint32_t w2 = shfl_u32(pf[kp][2], src0 + 2);
                uint32_t w3 = shfl_u32(pf[kp][3], src0 + 2);
                pa[3] = odd ? w3 : w2;
            }
#pragma unroll
            for (int nt = 0; nt < 16; nt++) {
                uint32_t bf2[2];
                bf2[0] = __float_as_uint(Vs[(kp * 8 + lc) * VP + nt * 8 + lr]);
                bf2[1] = __float_as_uint(Vs[(kp * 8 + lc + 4) * VP + nt * 8 + lr]);
                mma_tf32(of[nt], pa, bf2);
            }
        }
        __syncthreads();
    }

    const float invl0 = 1.0f / l0;
    const float invl1 = 1.0f / l1;
    float* Ob = O + (size_t)qbase * HID + hcol;
#pragma unroll
    for (int nt = 0; nt < 16; nt++) {
        const int c = nt * 8 + 2 * lc;
        float2 v0, v1;
        v0.x = __uint_as_float(f2tf(of[nt][0] * invl0));
        v0.y = __uint_as_float(f2tf(of[nt][1] * invl0));
        v1.x = __uint_as_float(f2tf(of[nt][2] * invl1));
        v1.y = __uint_as_float(f2tf(of[nt][3] * invl1));
        *(float2*)(Ob + (size_t)lr * HID + c) = v0;
        *(float2*)(Ob + (size_t)(lr + 8) * HID + c) = v1;
    }
}

// ===========================================================================
extern "C" void kernel_launch(void* const* d_in, const int* in_sizes, int n_in,
                              void* d_out, int out_size)
{
    const float* X  = (const float*)d_in[0];
    const float* Wq = (const float*)d_in[1];
    const float* bq = (const float*)d_in[2];
    const float* Wk = (const float*)d_in[3];
    const float* bk = (const float*)d_in[4];
    const float* Wv = (const float*)d_in[5];
    const float* bv = (const float*)d_in[6];
    const float* Wo = (const float*)d_in[7];
    const float* bo = (const float*)d_in[8];
    const float* order_gate   = (const float*)d_in[11];
    const float* justice_gate = (const float*)d_in[12];
    float* out = (float*)d_out;

    float *qp, *kp, *vp, *op, *xr, *w0, *w1, *w2, *w3;
    cudaGetSymbolAddress((void**)&qp, g_Q);
    cudaGetSymbolAddress((void**)&kp, g_K);
    cudaGetSymbolAddress((void**)&vp, g_V);
    cudaGetSymbolAddress((void**)&op, g_O);
    cudaGetSymbolAddress((void**)&xr, g_Xr);
    cudaGetSymbolAddress((void**)&w0, g_W0);
    cudaGetSymbolAddress((void**)&w1, g_W1);
    cudaGetSymbolAddress((void**)&w2, g_W2);
    cudaGetSymbolAddress((void**)&w3, g_W3);

    cudaFuncSetAttribute(gemm_qkv,
                         cudaFuncAttributeMaxDynamicSharedMemorySize,
                         GEMM_SMEM_BYTES);
    cudaFuncSetAttribute(gemm_single,
                         cudaFuncAttributeMaxDynamicSharedMemorySize,
                         GEMM_SMEM_BYTES);
    cudaFuncSetAttribute(flash_attn_tf32,
                         cudaFuncAttributeMaxDynamicSharedMemorySize,
                         FLASH_SMEM_BYTES);

    const int N4 = (HID * HID) / 4;

    // fused prepass: round all 5 inputs to tf32 in one launch
    dim3 rg((N4 + 255) / 256, 5);
    round_tf32_5<<<rg, 256>>>((const float4*)X,  (const float4*)Wq,
                              (const float4*)Wk, (const float4*)Wv,
                              (const float4*)Wo,
                              (float4*)xr, (float4*)w0, (float4*)w1,
                              (float4*)w2, (float4*)w3, N4);

    // fused QKV projections (one launch, z = 0/1/2)
    dim3 gq(HID / BN, SEQ / BM, 3);   // 8 x 16 x 3
    gemm_qkv<<<gq, 256, GEMM_SMEM_BYTES>>>(xr, w0, w1, w2, bq, bk, bv,
                                           qp, kp, vp);

    dim3 ga(SEQ / FAQ, NH);           // 16 x 16
    flash_attn_tf32<<<ga, 256, FLASH_SMEM_BYTES>>>(qp, kp, vp, op,
                                                   order_gate, justice_gate);

    dim3 gg(HID / BN, SEQ / BM);      // 8 x 16
    gemm_single<<<gg, 256, GEMM_SMEM_BYTES>>>(op, w3, bo, out);
}

// round 9
// speedup vs baseline: 1.8763x; 1.8763x over previous
#include <cuda_runtime.h>
#include <cuda_fp16.h>
#include <math.h>
#include <stdint.h>

#define SEQ   2048
#define HID   2048
#define HD    128
#define NH    16

// Scratch (device globals: allocation-free rule)
__device__ __half g_Qh[SEQ * HID];
__device__ __half g_Kh[SEQ * HID];
__device__ __half g_Vh[SEQ * HID];
__device__ __half g_Oh[SEQ * HID];
__device__ __half g_Xh[SEQ * HID];
__device__ __half g_W0h[HID * HID];
__device__ __half g_W1h[HID * HID];
__device__ __half g_W2h[HID * HID];
__device__ __half g_W3h[HID * HID];

// ===========================================================================
// Helpers
// ===========================================================================
__device__ __forceinline__ uint32_t smem_u32(const void* p) {
    uint32_t a;
    asm("{ .reg .u64 t; cvta.to.shared.u64 t, %1; cvt.u32.u64 %0, t; }"
        : "=r"(a) : "l"(p));
    return a;
}
__device__ __forceinline__ void cp_async16(uint32_t dst, const void* src) {
    asm volatile("cp.async.cg.shared.global [%0], [%1], 16;" :: "r"(dst), "l"(src));
}
#define CP_COMMIT() asm volatile("cp.async.commit_group;" ::: "memory")
#define CP_WAIT(n)  asm volatile("cp.async.wait_group %0;" :: "n"(n) : "memory")

__device__ __forceinline__ uint32_t pack_h2(float lo, float hi) {
    __half2 h = __floats2half2_rn(lo, hi);   // .x = lo (low 16 bits)
    return *(uint32_t*)&h;
}

// ldmatrix x4 b16 (native)
__device__ __forceinline__ void ldsm_x4(uint32_t r[4], uint32_t addr) {
    asm volatile("ldmatrix.sync.aligned.m8n8.x4.shared.b16 {%0,%1,%2,%3}, [%4];"
        : "=r"(r[0]), "=r"(r[1]), "=r"(r[2]), "=r"(r[3]) : "r"(addr));
}
__device__ __forceinline__ void ldsm_x4_t(uint32_t r[4], uint32_t addr) {
    asm volatile("ldmatrix.sync.aligned.m8n8.x4.trans.shared.b16 {%0,%1,%2,%3}, [%4];"
        : "=r"(r[0]), "=r"(r[1]), "=r"(r[2]), "=r"(r[3]) : "r"(addr));
}

// C[16x8] += A[16x16] * B[8x16]^T   (fp16 in, fp32 accum)
__device__ __forceinline__ void mma_f16(float c[4], const uint32_t a[4],
                                        const uint32_t b[2]) {
    asm volatile(
        "mma.sync.aligned.m16n8k16.row.col.f32.f16.f16.f32 "
        "{%0,%1,%2,%3}, {%4,%5,%6,%7}, {%8,%9}, {%0,%1,%2,%3};"
        : "+f"(c[0]), "+f"(c[1]), "+f"(c[2]), "+f"(c[3])
        : "r"(a[0]), "r"(a[1]), "r"(a[2]), "r"(a[3]), "r"(b[0]), "r"(b[1]));
}

// ===========================================================================
// Fused fp32 -> fp16 conversion prepass (5 tensors, one launch)
// ===========================================================================
__global__ __launch_bounds__(256) void cvt_f16_5(
    const float4* __restrict__ i0, const float4* __restrict__ i1,
    const float4* __restrict__ i2, const float4* __restrict__ i3,
    const float4* __restrict__ i4,
    __half* __restrict__ o0, __half* __restrict__ o1,
    __half* __restrict__ o2, __half* __restrict__ o3,
    __half* __restrict__ o4, int n4)
{
    const int z = blockIdx.y;
    const float4* in = (z == 0) ? i0 : (z == 1) ? i1 : (z == 2) ? i2
                      : (z == 3) ? i3 : i4;
    __half* out      = (z == 0) ? o0 : (z == 1) ? o1 : (z == 2) ? o2
                      : (z == 3) ? o3 : o4;
    int i = blockIdx.x * blockDim.x + threadIdx.x;
    if (i >= n4) return;
    float4 v = in[i];
    uint2 h;
    h.x = pack_h2(v.x, v.y);
    h.y = pack_h2(v.z, v.w);
    ((uint2*)out)[i] = h;
}

// ===========================================================================
// fp16 mma.sync GEMM core:  C[M,N] = A[M,K] @ B[N,K]^T + bias[N]
// CTA 128x256, 8 warps (2x4) of 64x64, BK=64 halfs, 3-stage cp.async,
// native ldmatrix.x4 fragment loads.
// HALF_OUT: store fp16 (feeds downstream fp16 MMAs); else fp32.
// ===========================================================================
#define BM 128
#define BN 256
#define BK 64
#define NST 3
#define ROWPH 72                            // halfs; 144B rows, conflict-free
#define ATFH (BM * ROWPH)                   // 9216 halfs
#define BTFH (BN * ROWPH)                   // 18432 halfs
#define STFH (ATFH + BTFH)                  // 27648 halfs = 55296 B / stage
#define GEMM_SMEM_BYTES (NST * STFH * 2)    // 165888

__device__ __forceinline__ void gemm_load_stage(
    const __half* __restrict__ Ab, const __half* __restrict__ Bb,
    __half* sm, int slot, int k0, int tid)
{
    const uint32_t sbase = smem_u32(sm) + (uint32_t)(slot * STFH) * 2u;
#pragma unroll
    for (int it = 0; it < 12; it++) {
        const int idx = tid + it * 256;       // 0..3071
        const int r = idx >> 3;               // 0..383
        const int q = idx & 7;                // 8-half (16B) segment
        const __half* src = (r < BM) ? (Ab + (size_t)r * HID + k0 + q * 8)
                                     : (Bb + (size_t)(r - BM) * HID + k0 + q * 8);
        cp_async16(sbase + (uint32_t)(r * ROWPH + q * 8) * 2u, src);
    }
}

template <bool HALF_OUT>
__device__ __forceinline__ void gemm_body(
    const __half* __restrict__ A, const __half* __restrict__ B,
    const float* __restrict__ bias, void* __restrict__ Cv,
    __half* sm, int row0, int col0)
{
    const int tid  = threadIdx.x;
    const int wid  = tid >> 5;
    const int lane = tid & 31;
    const int lr   = lane >> 2;
    const int lc   = lane & 3;
    const int l15  = lane & 15;
    const int klo  = (lane >> 4) << 3;     // 0 or 8 halfs
    const int wm   = (wid >> 2) * 64;
    const int wn   = (wid & 3) * 64;

    const __half* Ab = A + (size_t)row0 * HID;
    const __half* Bb = B + (size_t)col0 * HID;

    float acc[4][8][4];
#pragma unroll
    for (int mt = 0; mt < 4; mt++)
#pragma unroll
        for (int nt = 0; nt < 8; nt++)
#pragma unroll
            for (int i = 0; i < 4; i++) acc[mt][nt][i] = 0.0f;

#pragma unroll
    for (int s = 0; s < NST - 1; s++) {
        gemm_load_stage(Ab, Bb, sm, s, s * BK, tid);
        CP_COMMIT();
    }

    const uint32_t sbase = smem_u32(sm);
    const int KCH = HID / BK;   // 32
    for (int j = 0; j < KCH; j++) {
        if (j + NST - 1 < KCH) {
            gemm_load_stage(Ab, Bb, sm, (j + NST - 1) % NST, (j + NST - 1) * BK, tid);
        }
        CP_COMMIT();
        CP_WAIT(NST - 1);
        __syncthreads();

        const uint32_t sa = sbase + (uint32_t)((j % NST) * STFH) * 2u;
        const uint32_t sb = sa + (uint32_t)ATFH * 2u;

#pragma unroll
        for (int kk = 0; kk < BK; kk += 16) {
            uint32_t af[4][4], bf[8][2];
#pragma unroll
            for (int mt = 0; mt < 4; mt++)
                ldsm_x4(af[mt],
                        sa + (uint32_t)((wm + mt * 16 + l15) * ROWPH + kk + klo) * 2u);
#pragma unroll
            for (int np = 0; np < 4; np++) {
                uint32_t t[4];
                ldsm_x4(t,
                        sb + (uint32_t)((wn + np * 16 + l15) * ROWPH + kk + klo) * 2u);
                bf[2 * np + 0][0] = t[0];
                bf[2 * np + 1][0] = t[1];
                bf[2 * np + 0][1] = t[2];
                bf[2 * np + 1][1] = t[3];
            }
#pragma unroll
            for (int mt = 0; mt < 4; mt++)
#pragma unroll
                for (int nt = 0; nt < 8; nt++)
                    mma_f16(acc[mt][nt], af[mt], bf[nt]);
        }
        __syncthreads();
    }

#pragma unroll
    for (int mt = 0; mt < 4; mt++) {
#pragma unroll
        for (int half = 0; half < 2; half++) {
            const int r = row0 + wm + mt * 16 + lr + half * 8;
#pragma unroll
            for (int nt = 0; nt < 8; nt++) {
                const int c = col0 + wn + nt * 8 + 2 * lc;
                const float vx = acc[mt][nt][half * 2 + 0] + bias[c];
                const float vy = acc[mt][nt][half * 2 + 1] + bias[c + 1];
                if (HALF_OUT) {
                    __half* crow = (__half*)Cv + (size_t)r * HID;
                    *(uint32_t*)(crow + c) = pack_h2(vx, vy);
                } else {
                    float* crow = (float*)Cv + (size_t)r * HID;
                    *(float2*)(crow + c) = make_float2(vx, vy);
                }
            }
        }
    }
}

// Fused QKV projection: blockIdx.z selects weight/bias/output.
__global__ __launch_bounds__(256, 1) void gemm_qkv(
    const __half* __restrict__ A,
    const __half* __restrict__ W0, const __half* __restrict__ W1,
    const __half* __restrict__ W2,
    const float* __restrict__ b0, const float* __restrict__ b1,
    const float* __restrict__ b2,
    __half* __restrict__ C0, __half* __restrict__ C1, __half* __restrict__ C2)
{
    extern __shared__ __half smh[];
    const int z = blockIdx.z;
    const __half* B   = (z == 0) ? W0 : (z == 1) ? W1 : W2;
    const float* bias = (z == 0) ? b0 : (z == 1) ? b1 : b2;
    __half* C         = (z == 0) ? C0 : (z == 1) ? C1 : C2;
    gemm_body<true>(A, B, bias, C, smh, blockIdx.y * BM, blockIdx.x * BN);
}

// Output projection (fp32 result)
__global__ __launch_bounds__(256, 1) void gemm_single(
    const __half* __restrict__ A, const __half* __restrict__ B,
    const float* __restrict__ bias, float* __restrict__ C)
{
    extern __shared__ __half smh[];
    gemm_body<false>(A, B, bias, C, smh, blockIdx.y * BM, blockIdx.x * BN);
}

// ===========================================================================
// Flash attention, fp16 mma.sync (m16n8k16).
// 1 CTA = 128 q-rows x 1 head, 8 warps, each warp 16 q-rows end-to-end.
// K via ldmatrix.x4 (n-major); V via ldmatrix.x4.trans (k-major).
// P C-frag -> A-frag is pure in-thread f16x2 packing (no shuffles).
// ===========================================================================
#define FAQ 128
#define FSK 64
#define KPH 136                       // halfs: 272B rows, conflict-free
#define KTILEH (FSK * KPH)            // 8704 halfs = 17408 B
#define FSTAGEH (2 * KTILEH)          // K + V
#define FLASH_SMEM_BYTES (2 * FSTAGEH * 2)   // 69632

__device__ __forceinline__ void flash_load_kv(
    const __half* __restrict__ K, const __half* __restrict__ V,
    __half* sm, int slot, int kt, int hcol, int tid)
{
    const uint32_t ka = smem_u32(sm) + (uint32_t)(slot * FSTAGEH) * 2u;
    const uint32_t va = ka + (uint32_t)KTILEH * 2u;
    const int base = kt * FSK;
#pragma unroll
    for (int it = 0; it < 4; it++) {
        const int idx = tid + it * 256;     // 0..1023
        const int r = idx >> 4;             // 0..63
        const int q = idx & 15;             // 8-half segments
        cp_async16(ka + (uint32_t)(r * KPH + q * 8) * 2u,
                   K + (size_t)(base + r) * HID + hcol + q * 8);
        cp_async16(va + (uint32_t)(r * KPH + q * 8) * 2u,
                   V + (size_t)(base + r) * HID + hcol + q * 8);
    }
}

__global__ __launch_bounds__(256, 1) void flash_attn_f16(
    const __half* __restrict__ Q, const __half* __restrict__ K,
    const __half* __restrict__ V, __half* __restrict__ O,
    const float* __restrict__ order_gate, const float* __restrict__ justice_gate)
{
    extern __shared__ __half fsmh[];

    const int tid  = threadIdx.x;
    const int wid  = tid >> 5;
    const int lane = tid & 31;
    const int lr   = lane >> 2;
    const int lc   = lane & 3;
    const int l15  = lane & 15;
    const int klo  = (lane >> 4) << 3;
    const int hcol = blockIdx.y * HD;
    const int qbase = blockIdx.x * FAQ + wid * 16;

    const float sig_j = 1.0f / (1.0f + __expf(-justice_gate[0]));
    const float sig_o = 1.0f / (1.0f + __expf(-order_gate[0]));
    const float alpha = (1.0f - 0.1f * sig_j) * rsqrtf((float)HD);
    const float obias = sig_o * 0.05f / (float)SEQ;

    // Q fragments (8 k16 chunks), register-resident, loaded straight from gmem
    uint32_t qf[8][4];
    {
        const __half* Qb = Q + (size_t)qbase * HID + hcol;
#pragma unroll
        for (int ks = 0; ks < 8; ks++) {
            qf[ks][0] = *(const uint32_t*)(Qb + (size_t)lr * HID + ks * 16 + 2 * lc);
            qf[ks][1] = *(const uint32_t*)(Qb + (size_t)(lr + 8) * HID + ks * 16 + 2 * lc);
            qf[ks][2] = *(const uint32_t*)(Qb + (size_t)lr * HID + ks * 16 + 2 * lc + 8);
            qf[ks][3] = *(const uint32_t*)(Qb + (size_t)(lr + 8) * HID + ks * 16 + 2 * lc + 8);
        }
    }

    float m0 = -1.0e30f, m1 = -1.0e30f, l0 = 0.0f, l1 = 0.0f;
    float of[16][4];
#pragma unroll
    for (int nt = 0; nt < 16; nt++)
#pragma unroll
        for (int i = 0; i < 4; i++) of[nt][i] = 0.0f;

    flash_load_kv(K, V, fsmh, 0, 0, hcol, tid);
    CP_COMMIT();

    const int NT = SEQ / FSK;   // 32
    for (int kt = 0; kt < NT; kt++) {
        if (kt + 1 < NT) {
            flash_load_kv(K, V, fsmh, (kt + 1) & 1, kt + 1, hcol, tid);
            CP_COMMIT();
            CP_WAIT(1);
        } else {
            CP_WAIT(0);
        }
        __syncthreads();

        const uint32_t ksa = smem_u32(fsmh) + (uint32_t)((kt & 1) * FSTAGEH) * 2u;
        const uint32_t vsa = ksa + (uint32_t)KTILEH * 2u;

        // S = Q K^T : 8 k16 steps over d=128
        float sf[8][4];
#pragma unroll
        for (int nt = 0; nt < 8; nt++)
#pragma unroll
            for (int i = 0; i < 4; i++) sf[nt][i] = 0.0f;

#pragma unroll
        for (int ks = 0; ks < 8; ks++) {
            uint32_t bf[8][2];
#pragma unroll
            for (int np = 0; np < 4; np++) {
                uint32_t t[4];
                ldsm_x4(t, ksa + (uint32_t)((np * 16 + l15) * KPH + ks * 16 + klo) * 2u);
                bf[2 * np + 0][0] = t[0];
                bf[2 * np + 1][0] = t[1];
                bf[2 * np + 0][1] = t[2];
                bf[2 * np + 1][1] = t[3];
            }
#pragma unroll
            for (int nt = 0; nt < 8; nt++)
                mma_f16(sf[nt], qf[ks], bf[nt]);
        }

        // scale + key position bias; row max
        float rmax0 = -1.0e30f, rmax1 = -1.0e30f;
#pragma unroll
        for (int nt = 0; nt < 8; nt++) {
            const float col0 = (float)(kt * FSK + nt * 8 + 2 * lc);
            sf[nt][0] = fmaf(sf[nt][0], alpha, obias * col0);
            sf[nt][1] = fmaf(sf[nt][1], alpha, obias * (col0 + 1.0f));
            sf[nt][2] = fmaf(sf[nt][2], alpha, obias * col0);
            sf[nt][3] = fmaf(sf[nt][3], alpha, obias * (col0 + 1.0f));
            rmax0 = fmaxf(rmax0, fmaxf(sf[nt][0], sf[nt][1]));
            rmax1 = fmaxf(rmax1, fmaxf(sf[nt][2], sf[nt][3]));
        }
#pragma unroll
        for (int off = 1; off < 4; off <<= 1) {
            rmax0 = fmaxf(rmax0, __shfl_xor_sync(0xffffffffu, rmax0, off));
            rmax1 = fmaxf(rmax1, __shfl_xor_sync(0xffffffffu, rmax1, off));
        }
        const float m0n = fmaxf(m0, rmax0);
        const float m1n = fmaxf(m1, rmax1);
        const float corr0 = __expf(m0 - m0n);
        const float corr1 = __expf(m1 - m1n);

        // exp + row sums + fp16 P fragments (in-thread pack, no shuffles)
        float rsum0 = 0.0f, rsum1 = 0.0f;
        uint32_t ph[8][2];
#pragma unroll
        for (int nt = 0; nt < 8; nt++) {
            const float e0 = __expf(sf[nt][0] - m0n);
            const float e1 = __expf(sf[nt][1] - m0n);
            const float e2 = __expf(sf[nt][2] - m1n);
            const float e3 = __expf(sf[nt][3] - m1n);
            rsum0 += e0 + e1;
            rsum1 += e2 + e3;
            ph[nt][0] = pack_h2(e0, e1);   // row lr,   keys {nt*8+2lc, +1}
            ph[nt][1] = pack_h2(e2, e3);   // row lr+8, same keys
        }
#pragma unroll
        for (int off = 1; off < 4; off <<= 1) {
            rsum0 += __shfl_xor_sync(0xffffffffu, rsum0, off);
            rsum1 += __shfl_xor_sync(0xffffffffu, rsum1, off);
        }
        l0 = l0 * corr0 + rsum0; m0 = m0n;
        l1 = l1 * corr1 + rsum1; m1 = m1n;

#pragma unroll
        for (int nt = 0; nt < 16; nt++) {
            of[nt][0] *= corr0; of[nt][1] *= corr0;
            of[nt][2] *= corr1; of[nt][3] *= corr1;
        }

        // O += P V : 4 k16 chunks over 64 keys; V via ldmatrix.trans
#pragma unroll
        for (int kp = 0; kp < 4; kp++) {
            uint32_t pa[4];
            pa[0] = ph[2 * kp + 0][0];
            pa[1] = ph[2 * kp + 0][1];
            pa[2] = ph[2 * kp + 1][0];
            pa[3] = ph[2 * kp + 1][1];
#pragma unroll
            for (int dg = 0; dg < 8; dg++) {
                uint32_t t[4];
                ldsm_x4_t(t, vsa + (uint32_t)((kp * 16 + l15) * KPH + dg * 16 + klo) * 2u);
                uint32_t b0[2] = {t[0], t[1]};
                uint32_t b1[2] = {t[2], t[3]};
                mma_f16(of[2 * dg + 0], pa, b0);
                mma_f16(of[2 * dg + 1], pa, b1);
            }
        }
        __syncthreads();
    }

    // normalize + fp16 write (feeds final fp16 GEMM)
    const float invl0 = 1.0f / l0;
    const float invl1 = 1.0f / l1;
    __half* Ob = O + (size_t)qbase * HID + hcol;
#pragma unroll
    for (int nt = 0; nt < 16; nt++) {
        const int c = nt * 8 + 2 * lc;
        *(uint32_t*)(Ob + (size_t)lr * HID + c) =
            pack_h2(of[nt][0] * invl0, of[nt][1] * invl0);
        *(uint32_t*)(Ob + (size_t)(lr + 8) * HID + c) =
            pack_h2(of[nt][2] * invl1, of[nt][3] * invl1);
    }
}

// ===========================================================================
extern "C" void kernel_launch(void* const* d_in, const int* in_sizes, int n_in,
                              void* d_out, int out_size)
{
    const float* X  = (const float*)d_in[0];
    const float* Wq = (const float*)d_in[1];
    const float* bq = (const float*)d_in[2];
    const float* Wk = (const float*)d_in[3];
    const float* bk = (const float*)d_in[4];
    const float* Wv = (const float*)d_in[5];
    const float* bv = (const float*)d_in[6];
    const float* Wo = (const float*)d_in[7];
    const float* bo = (const float*)d_in[8];
    const float* order_gate   = (const float*)d_in[11];
    const float* justice_gate = (const float*)d_in[12];
    float* out = (float*)d_out;

    __half *qp, *kp, *vp, *op, *xh, *w0, *w1, *w2, *w3;
    cudaGetSymbolAddress((void**)&qp, g_Qh);
    cudaGetSymbolAddress((void**)&kp, g_Kh);
    cudaGetSymbolAddress((void**)&vp, g_Vh);
    cudaGetSymbolAddress((void**)&op, g_Oh);
    cudaGetSymbolAddress((void**)&xh, g_Xh);
    cudaGetSymbolAddress((void**)&w0, g_W0h);
    cudaGetSymbolAddress((void**)&w1, g_W1h);
    cudaGetSymbolAddress((void**)&w2, g_W2h);
    cudaGetSymbolAddress((void**)&w3, g_W3h);

    cudaFuncSetAttribute(gemm_qkv,
                         cudaFuncAttributeMaxDynamicSharedMemorySize,
                         GEMM_SMEM_BYTES);
    cudaFuncSetAttribute(gemm_single,
                         cudaFuncAttributeMaxDynamicSharedMemorySize,
                         GEMM_SMEM_BYTES);
    cudaFuncSetAttribute(flash_attn_f16,
                         cudaFuncAttributeMaxDynamicSharedMemorySize,
                         FLASH_SMEM_BYTES);

    const int N4 = (HID * HID) / 4;

    // fused prepass: convert all 5 fp32 inputs to fp16 in one launch
    dim3 rg((N4 + 255) / 256, 5);
    cvt_f16_5<<<rg, 256>>>((const float4*)X,  (const float4*)Wq,
                           (const float4*)Wk, (const float4*)Wv,
                           (const float4*)Wo,
                           xh, w0, w1, w2, w3, N4);

    // fused QKV projections (one launch, z = 0/1/2)
    dim3 gq(HID / BN, SEQ / BM, 3);   // 8 x 16 x 3
    gemm_qkv<<<gq, 256, GEMM_SMEM_BYTES>>>(xh, w0, w1, w2, bq, bk, bv,
                                           qp, kp, vp);

    dim3 ga(SEQ / FAQ, NH);           // 16 x 16
    flash_attn_f16<<<ga, 256, FLASH_SMEM_BYTES>>>(qp, kp, vp, op,
                                                  order_gate, justice_gate);

    dim3 gg(HID / BN, SEQ / BM);      // 8 x 16
    gemm_single<<<gg, 256, GEMM_SMEM_BYTES>>>(op, w3, bo, out);
}

// round 10
// speedup vs baseline: 1.9036x; 1.0146x over previous
#include <cuda_runtime.h>
#include <cuda_fp16.h>
#include <math.h>
#include <stdint.h>

#define SEQ   2048
#define HID   2048
#define HD    128
#define NH    16

// Scratch (device globals: allocation-free rule)
__device__ __half g_Qh[SEQ * HID];
__device__ __half g_Kh[SEQ * HID];
__device__ __half g_Vh[SEQ * HID];
__device__ __half g_Oh[SEQ * HID];
__device__ __half g_Xh[SEQ * HID];
__device__ __half g_W0h[HID * HID];
__device__ __half g_W1h[HID * HID];
__device__ __half g_W2h[HID * HID];
__device__ __half g_W3h[HID * HID];

// ===========================================================================
// Helpers
// ===========================================================================
__device__ __forceinline__ uint32_t smem_u32(const void* p) {
    uint32_t a;
    asm("{ .reg .u64 t; cvta.to.shared.u64 t, %1; cvt.u32.u64 %0, t; }"
        : "=r"(a) : "l"(p));
    return a;
}
__device__ __forceinline__ void cp_async16(uint32_t dst, const void* src) {
    asm volatile("cp.async.cg.shared.global [%0], [%1], 16;" :: "r"(dst), "l"(src));
}
#define CP_COMMIT() asm volatile("cp.async.commit_group;" ::: "memory")
#define CP_WAIT(n)  asm volatile("cp.async.wait_group %0;" :: "n"(n) : "memory")

__device__ __forceinline__ uint32_t pack_h2(float lo, float hi) {
    __half2 h = __floats2half2_rn(lo, hi);   // .x = lo (low 16 bits)
    return *(uint32_t*)&h;
}

// ldmatrix x4 b16 (native)
__device__ __forceinline__ void ldsm_x4(uint32_t r[4], uint32_t addr) {
    asm volatile("ldmatrix.sync.aligned.m8n8.x4.shared.b16 {%0,%1,%2,%3}, [%4];"
        : "=r"(r[0]), "=r"(r[1]), "=r"(r[2]), "=r"(r[3]) : "r"(addr));
}
__device__ __forceinline__ void ldsm_x4_t(uint32_t r[4], uint32_t addr) {
    asm volatile("ldmatrix.sync.aligned.m8n8.x4.trans.shared.b16 {%0,%1,%2,%3}, [%4];"
        : "=r"(r[0]), "=r"(r[1]), "=r"(r[2]), "=r"(r[3]) : "r"(addr));
}

// C[16x8] += A[16x16] * B[8x16]^T   (fp16 in, fp32 accum)
__device__ __forceinline__ void mma_f16(float c[4], const uint32_t a[4],
                                        const uint32_t b[2]) {
    asm volatile(
        "mma.sync.aligned.m16n8k16.row.col.f32.f16.f16.f32 "
        "{%0,%1,%2,%3}, {%4,%5,%6,%7}, {%8,%9}, {%0,%1,%2,%3};"
        : "+f"(c[0]), "+f"(c[1]), "+f"(c[2]), "+f"(c[3])
        : "r"(a[0]), "r"(a[1]), "r"(a[2]), "r"(a[3]), "r"(b[0]), "r"(b[1]));
}

// ===========================================================================
// Fused fp32 -> fp16 conversion prepass (5 tensors, one launch)
// ===========================================================================
__global__ __launch_bounds__(256) void cvt_f16_5(
    const float4* __restrict__ i0, const float4* __restrict__ i1,
    const float4* __restrict__ i2, const float4* __restrict__ i3,
    const float4* __restrict__ i4,
    __half* __restrict__ o0, __half* __restrict__ o1,
    __half* __restrict__ o2, __half* __restrict__ o3,
    __half* __restrict__ o4, int n4)
{
    const int z = blockIdx.y;
    const float4* in = (z == 0) ? i0 : (z == 1) ? i1 : (z == 2) ? i2
                      : (z == 3) ? i3 : i4;
    __half* out      = (z == 0) ? o0 : (z == 1) ? o1 : (z == 2) ? o2
                      : (z == 3) ? o3 : o4;
    int i = blockIdx.x * blockDim.x + threadIdx.x;
    if (i >= n4) return;
    float4 v = in[i];
    uint2 h;
    h.x = pack_h2(v.x, v.y);
    h.y = pack_h2(v.z, v.w);
    ((uint2*)out)[i] = h;
}

// ===========================================================================
// fp16 mma.sync GEMM core:  C[M,N] = A[M,K] @ B[N,K]^T + bias[N]
// CTA 128x256, 8 warps (2x4) of 64x64, BK=64 halfs, 3-stage cp.async,
// SINGLE __syncthreads per K-chunk (wait -> sync -> issue-next -> compute).
// HALF_OUT: store fp16 (feeds downstream fp16 MMAs); else fp32.
// ===========================================================================
#define BM 128
#define BN 256
#define BK 64
#define NST 3
#define ROWPH 72                            // halfs; 144B rows, conflict-free
#define ATFH (BM * ROWPH)                   // 9216 halfs
#define BTFH (BN * ROWPH)                   // 18432 halfs
#define STFH (ATFH + BTFH)                  // 27648 halfs = 55296 B / stage
#define GEMM_SMEM_BYTES (NST * STFH * 2)    // 165888

__device__ __forceinline__ void gemm_load_stage(
    const __half* __restrict__ Ab, const __half* __restrict__ Bb,
    __half* sm, int slot, int k0, int tid)
{
    const uint32_t sbase = smem_u32(sm) + (uint32_t)(slot * STFH) * 2u;
#pragma unroll
    for (int it = 0; it < 12; it++) {
        const int idx = tid + it * 256;       // 0..3071
        const int r = idx >> 3;               // 0..383
        const int q = idx & 7;                // 8-half (16B) segment
        const __half* src = (r < BM) ? (Ab + (size_t)r * HID + k0 + q * 8)
                                     : (Bb + (size_t)(r - BM) * HID + k0 + q * 8);
        cp_async16(sbase + (uint32_t)(r * ROWPH + q * 8) * 2u, src);
    }
}

template <bool HALF_OUT>
__device__ __forceinline__ void gemm_body(
    const __half* __restrict__ A, const __half* __restrict__ B,
    const float* __restrict__ bias, void* __restrict__ Cv,
    __half* sm, int row0, int col0)
{
    const int tid  = threadIdx.x;
    const int wid  = tid >> 5;
    const int lane = tid & 31;
    const int lr   = lane >> 2;
    const int lc   = lane & 3;
    const int l15  = lane & 15;
    const int klo  = (lane >> 4) << 3;     // 0 or 8 halfs
    const int wm   = (wid >> 2) * 64;
    const int wn   = (wid & 3) * 64;

    const __half* Ab = A + (size_t)row0 * HID;
    const __half* Bb = B + (size_t)col0 * HID;

    float acc[4][8][4];
#pragma unroll
    for (int mt = 0; mt < 4; mt++)
#pragma unroll
        for (int nt = 0; nt < 8; nt++)
#pragma unroll
            for (int i = 0; i < 4; i++) acc[mt][nt][i] = 0.0f;

#pragma unroll
    for (int s = 0; s < NST - 1; s++) {
        gemm_load_stage(Ab, Bb, sm, s, s * BK, tid);
        CP_COMMIT();
    }

    const uint32_t sbase = smem_u32(sm);
    const int KCH = HID / BK;   // 32
    for (int j = 0; j < KCH; j++) {
        CP_WAIT(NST - 2);         // chunk j resident
        __syncthreads();          // all warps done reading slot (j+NST-1)%NST
        if (j + NST - 1 < KCH) {
            gemm_load_stage(Ab, Bb, sm, (j + NST - 1) % NST, (j + NST - 1) * BK, tid);
        }
        CP_COMMIT();              // may be empty near the tail (keeps group math exact)

        const uint32_t sa = sbase + (uint32_t)((j % NST) * STFH) * 2u;
        const uint32_t sb = sa + (uint32_t)ATFH * 2u;

#pragma unroll
        for (int kk = 0; kk < BK; kk += 16) {
            uint32_t af[4][4], bf[8][2];
#pragma unroll
            for (int mt = 0; mt < 4; mt++)
                ldsm_x4(af[mt],
                        sa + (uint32_t)((wm + mt * 16 + l15) * ROWPH + kk + klo) * 2u);
#pragma unroll
            for (int np = 0; np < 4; np++) {
                uint32_t t[4];
                ldsm_x4(t,
                        sb + (uint32_t)((wn + np * 16 + l15) * ROWPH + kk + klo) * 2u);
                bf[2 * np + 0][0] = t[0];
                bf[2 * np + 1][0] = t[1];
                bf[2 * np + 0][1] = t[2];
                bf[2 * np + 1][1] = t[3];
            }
#pragma unroll
            for (int mt = 0; mt < 4; mt++)
#pragma unroll
                for (int nt = 0; nt < 8; nt++)
                    mma_f16(acc[mt][nt], af[mt], bf[nt]);
        }
    }

#pragma unroll
    for (int mt = 0; mt < 4; mt++) {
#pragma unroll
        for (int half = 0; half < 2; half++) {
            const int r = row0 + wm + mt * 16 + lr + half * 8;
#pragma unroll
            for (int nt = 0; nt < 8; nt++) {
                const int c = col0 + wn + nt * 8 + 2 * lc;
                const float vx = acc[mt][nt][half * 2 + 0] + bias[c];
                const float vy = acc[mt][nt][half * 2 + 1] + bias[c + 1];
                if (HALF_OUT) {
                    __half* crow = (__half*)Cv + (size_t)r * HID;
                    *(uint32_t*)(crow + c) = pack_h2(vx, vy);
                } else {
                    float* crow = (float*)Cv + (size_t)r * HID;
                    *(float2*)(crow + c) = make_float2(vx, vy);
                }
            }
        }
    }
}

// Fused QKV projection: blockIdx.z selects weight/bias/output.
__global__ __launch_bounds__(256, 1) void gemm_qkv(
    const __half* __restrict__ A,
    const __half* __restrict__ W0, const __half* __restrict__ W1,
    const __half* __restrict__ W2,
    const float* __restrict__ b0, const float* __restrict__ b1,
    const float* __restrict__ b2,
    __half* __restrict__ C0, __half* __restrict__ C1, __half* __restrict__ C2)
{
    extern __shared__ __half smh[];
    const int z = blockIdx.z;
    const __half* B   = (z == 0) ? W0 : (z == 1) ? W1 : W2;
    const float* bias = (z == 0) ? b0 : (z == 1) ? b1 : b2;
    __half* C         = (z == 0) ? C0 : (z == 1) ? C1 : C2;
    gemm_body<true>(A, B, bias, C, smh, blockIdx.y * BM, blockIdx.x * BN);
}

// Output projection (fp32 result)
__global__ __launch_bounds__(256, 1) void gemm_single(
    const __half* __restrict__ A, const __half* __restrict__ B,
    const float* __restrict__ bias, float* __restrict__ C)
{
    extern __shared__ __half smh[];
    gemm_body<false>(A, B, bias, C, smh, blockIdx.y * BM, blockIdx.x * BN);
}

// ===========================================================================
// Flash attention, fp16 mma.sync (m16n8k16).
// 1 CTA = 128 q-rows x 1 head, 8 warps, each warp 16 q-rows end-to-end.
// 3-slot KV ring, SINGLE __syncthreads per tile.
// K via ldmatrix.x4 (n-major); V via ldmatrix.x4.trans (k-major).
// ===========================================================================
#define FAQ 128
#define FSK 64
#define FSTG 3
#define KPH 136                       // halfs: 272B rows, conflict-free
#define KTILEH (FSK * KPH)            // 8704 halfs = 17408 B
#define FSTAGEH (2 * KTILEH)          // K + V : 34816 B
#define FLASH_SMEM_BYTES (FSTG * FSTAGEH * 2)   // 104448

__device__ __forceinline__ void flash_load_kv(
    const __half* __restrict__ K, const __half* __restrict__ V,
    __half* sm, int slot, int kt, int hcol, int tid)
{
    const uint32_t ka = smem_u32(sm) + (uint32_t)(slot * FSTAGEH) * 2u;
    const uint32_t va = ka + (uint32_t)KTILEH * 2u;
    const int base = kt * FSK;
#pragma unroll
    for (int it = 0; it < 4; it++) {
        const int idx = tid + it * 256;     // 0..1023
        const int r = idx >> 4;             // 0..63
        const int q = idx & 15;             // 8-half segments
        cp_async16(ka + (uint32_t)(r * KPH + q * 8) * 2u,
                   K + (size_t)(base + r) * HID + hcol + q * 8);
        cp_async16(va + (uint32_t)(r * KPH + q * 8) * 2u,
                   V + (size_t)(base + r) * HID + hcol + q * 8);
    }
}

__global__ __launch_bounds__(256, 1) void flash_attn_f16(
    const __half* __restrict__ Q, const __half* __restrict__ K,
    const __half* __restrict__ V, __half* __restrict__ O,
    const float* __restrict__ order_gate, const float* __restrict__ justice_gate)
{
    extern __shared__ __half fsmh[];

    const int tid  = threadIdx.x;
    const int wid  = tid >> 5;
    const int lane = tid & 31;
    const int lr   = lane >> 2;
    const int lc   = lane & 3;
    const int l15  = lane & 15;
    const int klo  = (lane >> 4) << 3;
    const int hcol = blockIdx.y * HD;
    const int qbase = blockIdx.x * FAQ + wid * 16;

    const float sig_j = 1.0f / (1.0f + __expf(-justice_gate[0]));
    const float sig_o = 1.0f / (1.0f + __expf(-order_gate[0]));
    const float alpha = (1.0f - 0.1f * sig_j) * rsqrtf((float)HD);
    const float obias = sig_o * 0.05f / (float)SEQ;

    // Q fragments (8 k16 chunks), register-resident, loaded straight from gmem
    uint32_t qf[8][4];
    {
        const __half* Qb = Q + (size_t)qbase * HID + hcol;
#pragma unroll
        for (int ks = 0; ks < 8; ks++) {
            qf[ks][0] = *(const uint32_t*)(Qb + (size_t)lr * HID + ks * 16 + 2 * lc);
            qf[ks][1] = *(const uint32_t*)(Qb + (size_t)(lr + 8) * HID + ks * 16 + 2 * lc);
            qf[ks][2] = *(const uint32_t*)(Qb + (size_t)lr * HID + ks * 16 + 2 * lc + 8);
            qf[ks][3] = *(const uint32_t*)(Qb + (size_t)(lr + 8) * HID + ks * 16 + 2 * lc + 8);
        }
    }

    float m0 = -1.0e30f, m1 = -1.0e30f, l0 = 0.0f, l1 = 0.0f;
    float of[16][4];
#pragma unroll
    for (int nt = 0; nt < 16; nt++)
#pragma unroll
        for (int i = 0; i < 4; i++) of[nt][i] = 0.0f;

    flash_load_kv(K, V, fsmh, 0, 0, hcol, tid);
    CP_COMMIT();
    flash_load_kv(K, V, fsmh, 1, 1, hcol, tid);
    CP_COMMIT();

    const int NT = SEQ / FSK;   // 32
    for (int kt = 0; kt < NT; kt++) {
        CP_WAIT(1);             // tile kt resident
        __syncthreads();        // all warps done reading slot (kt+2)%FSTG
        if (kt + 2 < NT) {
            flash_load_kv(K, V, fsmh, (kt + 2) % FSTG, kt + 2, hcol, tid);
        }
        CP_COMMIT();            // may be empty near the tail

        const uint32_t ksa = smem_u32(fsmh) + (uint32_t)((kt % FSTG) * FSTAGEH) * 2u;
        const uint32_t vsa = ksa + (uint32_t)KTILEH * 2u;

        // S = Q K^T : 8 k16 steps over d=128
        float sf[8][4];
#pragma unroll
        for (int nt = 0; nt < 8; nt++)
#pragma unroll
            for (int i = 0; i < 4; i++) sf[nt][i] = 0.0f;

#pragma unroll
        for (int ks = 0; ks < 8; ks++) {
            uint32_t bf[8][2];
#pragma unroll
            for (int np = 0; np < 4; np++) {
                uint32_t t[4];
                ldsm_x4(t, ksa + (uint32_t)((np * 16 + l15) * KPH + ks * 16 + klo) * 2u);
                bf[2 * np + 0][0] = t[0];
                bf[2 * np + 1][0] = t[1];
                bf[2 * np + 0][1] = t[2];
                bf[2 * np + 1][1] = t[3];
            }
#pragma unroll
            for (int nt = 0; nt < 8; nt++)
                mma_f16(sf[nt], qf[ks], bf[nt]);
        }

        // scale + key position bias; row max
        float rmax0 = -1.0e30f, rmax1 = -1.0e30f;
#pragma unroll
        for (int nt = 0; nt < 8; nt++) {
            const float col0 = (float)(kt * FSK + nt * 8 + 2 * lc);
            sf[nt][0] = fmaf(sf[nt][0], alpha, obias * col0);
            sf[nt][1] = fmaf(sf[nt][1], alpha, obias * (col0 + 1.0f));
            sf[nt][2] = fmaf(sf[nt][2], alpha, obias * col0);
            sf[nt][3] = fmaf(sf[nt][3], alpha, obias * (col0 + 1.0f));
            rmax0 = fmaxf(rmax0, fmaxf(sf[nt][0], sf[nt][1]));
            rmax1 = fmaxf(rmax1, fmaxf(sf[nt][2], sf[nt][3]));
        }
#pragma unroll
        for (int off = 1; off < 4; off <<= 1) {
            rmax0 = fmaxf(rmax0, __shfl_xor_sync(0xffffffffu, rmax0, off));
            rmax1 = fmaxf(rmax1, __shfl_xor_sync(0xffffffffu, rmax1, off));
        }
        const float m0n = fmaxf(m0, rmax0);
        const float m1n = fmaxf(m1, rmax1);
        const float corr0 = __expf(m0 - m0n);
        const float corr1 = __expf(m1 - m1n);

        // exp + row sums + fp16 P fragments (in-thread pack, no shuffles)
        float rsum0 = 0.0f, rsum1 = 0.0f;
        uint32_t ph[8][2];
#pragma unroll
        for (int nt = 0; nt < 8; nt++) {
            const float e0 = __expf(sf[nt][0] - m0n);
            const float e1 = __expf(sf[nt][1] - m0n);
            const float e2 = __expf(sf[nt][2] - m1n);
            const float e3 = __expf(sf[nt][3] - m1n);
            rsum0 += e0 + e1;
            rsum1 += e2 + e3;
            ph[nt][0] = pack_h2(e0, e1);   // row lr,   keys {nt*8+2lc, +1}
            ph[nt][1] = pack_h2(e2, e3);   // row lr+8, same keys
        }
#pragma unroll
        for (int off = 1; off < 4; off <<= 1) {
            rsum0 += __shfl_xor_sync(0xffffffffu, rsum0, off);
            rsum1 += __shfl_xor_sync(0xffffffffu, rsum1, off);
        }
        l0 = l0 * corr0 + rsum0; m0 = m0n;
        l1 = l1 * corr1 + rsum1; m1 = m1n;

#pragma unroll
        for (int nt = 0; nt < 16; nt++) {
            of[nt][0] *= corr0; of[nt][1] *= corr0;
            of[nt][2] *= corr1; of[nt][3] *= corr1;
        }

        // O += P V : 4 k16 chunks over 64 keys; V via ldmatrix.trans
#pragma unroll
        for (int kp = 0; kp < 4; kp++) {
            uint32_t pa[4];
            pa[0] = ph[2 * kp + 0][0];
            pa[1] = ph[2 * kp + 0][1];
            pa[2] = ph[2 * kp + 1][0];
            pa[3] = ph[2 * kp + 1][1];
#pragma unroll
            for (int dg = 0; dg < 8; dg++) {
                uint32_t t[4];
                ldsm_x4_t(t, vsa + (uint32_t)((kp * 16 + l15) * KPH + dg * 16 + klo) * 2u);
                uint32_t b0[2] = {t[0], t[1]};
                uint32_t b1[2] = {t[2], t[3]};
                mma_f16(of[2 * dg + 0], pa, b0);
                mma_f16(of[2 * dg + 1], pa, b1);
            }
        }
    }

    // normalize + fp16 write (feeds final fp16 GEMM)
    const float invl0 = 1.0f / l0;
    const float invl1 = 1.0f / l1;
    __half* Ob = O + (size_t)qbase * HID + hcol;
#pragma unroll
    for (int nt = 0; nt < 16; nt++) {
        const int c = nt * 8 + 2 * lc;
        *(uint32_t*)(Ob + (size_t)lr * HID + c) =
            pack_h2(of[nt][0] * invl0, of[nt][1] * invl0);
        *(uint32_t*)(Ob + (size_t)(lr + 8) * HID + c) =
            pack_h2(of[nt][2] * invl1, of[nt][3] * invl1);
    }
}

// ===========================================================================
extern "C" void kernel_launch(void* const* d_in, const int* in_sizes, int n_in,
                              void* d_out, int out_size)
{
    const float* X  = (const float*)d_in[0];
    const float* Wq = (const float*)d_in[1];
    const float* bq = (const float*)d_in[2];
    const float* Wk = (const float*)d_in[3];
    const float* bk = (const float*)d_in[4];
    const float* Wv = (const float*)d_in[5];
    const float* bv = (const float*)d_in[6];
    const float* Wo = (const float*)d_in[7];
    const float* bo = (const float*)d_in[8];
    const float* order_gate   = (const float*)d_in[11];
    const float* justice_gate = (const float*)d_in[12];
    float* out = (float*)d_out;

    __half *qp, *kp, *vp, *op, *xh, *w0, *w1, *w2, *w3;
    cudaGetSymbolAddress((void**)&qp, g_Qh);
    cudaGetSymbolAddress((void**)&kp, g_Kh);
    cudaGetSymbolAddress((void**)&vp, g_Vh);
    cudaGetSymbolAddress((void**)&op, g_Oh);
    cudaGetSymbolAddress((void**)&xh, g_Xh);
    cudaGetSymbolAddress((void**)&w0, g_W0h);
    cudaGetSymbolAddress((void**)&w1, g_W1h);
    cudaGetSymbolAddress((void**)&w2, g_W2h);
    cudaGetSymbolAddress((void**)&w3, g_W3h);

    cudaFuncSetAttribute(gemm_qkv,
                         cudaFuncAttributeMaxDynamicSharedMemorySize,
                         GEMM_SMEM_BYTES);
    cudaFuncSetAttribute(gemm_single,
                         cudaFuncAttributeMaxDynamicSharedMemorySize,
                         GEMM_SMEM_BYTES);
    cudaFuncSetAttribute(flash_attn_f16,
                         cudaFuncAttributeMaxDynamicSharedMemorySize,
                         FLASH_SMEM_BYTES);

    const int N4 = (HID * HID) / 4;

    // fused prepass: convert all 5 fp32 inputs to fp16 in one launch
    dim3 rg((N4 + 255) / 256, 5);
    cvt_f16_5<<<rg, 256>>>((const float4*)X,  (const float4*)Wq,
                           (const float4*)Wk, (const float4*)Wv,
                           (const float4*)Wo,
                           xh, w0, w1, w2, w3, N4);

    // fused QKV projections (one launch, z = 0/1/2)
    dim3 gq(HID / BN, SEQ / BM, 3);   // 8 x 16 x 3
    gemm_qkv<<<gq, 256, GEMM_SMEM_BYTES>>>(xh, w0, w1, w2, bq, bk, bv,
                                           qp, kp, vp);

    dim3 ga(SEQ / FAQ, NH);           // 16 x 16
    flash_attn_f16<<<ga, 256, FLASH_SMEM_BYTES>>>(qp, kp, vp, op,
                                                  order_gate, justice_gate);

    dim3 gg(HID / BN, SEQ / BM);      // 8 x 16
    gemm_single<<<gg, 256, GEMM_SMEM_BYTES>>>(op, w3, bo, out);
}